// round 14
// baseline (speedup 1.0000x reference)
#include <cuda_runtime.h>
#include <cuda_bf16.h>
#include <cuda_fp16.h>
#include <cstdint>

#define NN 100000
#define EE 1600000
#define DD 64
#define BN_EPS 1e-5f

// scan decomposition: 49 blocks x 256 threads x 8 elements = 100352 >= NN
#define SCAN_CH   8
#define SCAN_TPB  256
#define SCAN_PER_BLK (SCAN_TPB * SCAN_CH)
#define SCAN_NB   ((NN + SCAN_PER_BLK - 1) / SCAN_PER_BLK)   // 49

// ---------------- scratch (no allocations allowed) ----------------
__device__ float   g_mean[NN * DD];    // 25.6 MB  mean-aggregated neighbor feats
__device__ float   g_h   [NN * DD];    // 25.6 MB  partial / pre-BN activations
__device__ __half2 g_xh  [NN * DD / 2];// 12.8 MB  fp16 copy of x (gather source)
__device__ int     g_srcs[EE];         // 6.4 MB   src indices grouped by dst
__device__ int     g_cnt [NN];         // per-dst degree
__device__ int     g_off [NN];         // CSR offsets (exclusive scan of g_cnt)
__device__ int     g_cur [NN];         // scatter cursors (copy of g_off)
__device__ int     g_bsum[SCAN_NB];    // per-block count sums
__device__ int     g_bpre[SCAN_NB];    // exclusive prefix of block sums
__device__ float   g_bn  [2 * DD];     // [0:64) sum, [64:128) sumsq
__device__ float   g_bnsc[DD];         // per-feature BN scale
__device__ float   g_bnsh[DD];         // per-feature BN shift
__device__ float   g_WT  [2 * DD * DD];// transposed concat [Wl^T ; Wr^T], k-major
__device__ int     g_is64;

// ---------------- prep: dtype detect (block 0) + W transpose (block 1) -----
__global__ void prep_kernel(const void* ei,
                            const float* __restrict__ Wl,
                            const float* __restrict__ Wr) {
    int t = threadIdx.x;
    if (blockIdx.x == 0) {
        __shared__ int bad;
        if (t == 0) bad = 0;
        __syncthreads();
        const long long* p = (const long long*)ei;
        for (int j = t; j < 2048; j += blockDim.x) {
            long long v = p[j];
            if (v < 0 || v >= NN) bad = 1;
        }
        __syncthreads();
        if (t == 0) g_is64 = bad ? 0 : 1;
    } else {
        #pragma unroll
        for (int i = 0; i < 16; i++) {
            int idx = t + i * 256;          // 0..4095
            int d = idx >> 6, k = idx & 63;
            g_WT[k * 64 + d]        = Wl[idx];   // Wl[d][k]
            g_WT[(64 + k) * 64 + d] = Wr[idx];   // Wr[d][k]
        }
    }
}

// ---------------- 0b) x -> fp16 copy (runs on forked stream) ----------------
__global__ void xcvt_kernel(const float* __restrict__ x) {
    int i = blockIdx.x * blockDim.x + threadIdx.x;   // float4 index
    if (i >= NN * DD / 4) return;
    float4 v = ((const float4*)x)[i];
    __half2 h0 = __floats2half2_rn(v.x, v.y);
    __half2 h1 = __floats2half2_rn(v.z, v.w);
    uint2 u;
    u.x = *(unsigned*)&h0;
    u.y = *(unsigned*)&h1;
    *(uint2*)&g_xh[2 * i] = u;
}

// ---------------- 1) per-dst degree count (4 edges / thread) ----------------
__global__ void count_kernel(const void* __restrict__ ei) {
    int q = blockIdx.x * blockDim.x + threadIdx.x;   // quad index
    if (q >= EE / 4) return;
    int d0, d1, d2, d3;
    if (g_is64) {
        const longlong2* p = (const longlong2*)((const long long*)ei + EE);
        longlong2 a = p[q * 2 + 0];
        longlong2 b = p[q * 2 + 1];
        d0 = (int)a.x; d1 = (int)a.y; d2 = (int)b.x; d3 = (int)b.y;
    } else {
        int4 a = ((const int4*)((const int*)ei + EE))[q];
        d0 = a.x; d1 = a.y; d2 = a.z; d3 = a.w;
    }
    atomicAdd(&g_cnt[d0], 1);
    atomicAdd(&g_cnt[d1], 1);
    atomicAdd(&g_cnt[d2], 1);
    atomicAdd(&g_cnt[d3], 1);
}

// ---------------- 2a) per-block sums of counts ----------------
__global__ __launch_bounds__(SCAN_TPB) void scan1_kernel() {
    int t = threadIdx.x;
    int base = blockIdx.x * SCAN_PER_BLK + t * SCAN_CH;
    int s = 0;
    #pragma unroll
    for (int j = 0; j < SCAN_CH; j++) {
        int idx = base + j;
        if (idx < NN) s += g_cnt[idx];
    }
    int lane = t & 31, wid = t >> 5;
    #pragma unroll
    for (int o = 16; o > 0; o >>= 1) s += __shfl_down_sync(0xffffffffu, s, o);
    __shared__ int ws[SCAN_TPB / 32];
    if (lane == 0) ws[wid] = s;
    __syncthreads();
    if (t == 0) {
        int tot = 0;
        #pragma unroll
        for (int w = 0; w < SCAN_TPB / 32; w++) tot += ws[w];
        g_bsum[blockIdx.x] = tot;
    }
}

// ---------------- 2b) scan the 49 block sums (two warps) ----------------
__global__ void scan2_kernel() {
    int t = threadIdx.x;                 // 64 threads covers SCAN_NB=49
    int v = (t < SCAN_NB) ? g_bsum[t] : 0;
    __shared__ int sh[64];
    int lane = t & 31, wid = t >> 5;
    int s = v;
    #pragma unroll
    for (int o = 1; o < 32; o <<= 1) {
        int u = __shfl_up_sync(0xffffffffu, s, o);
        if (lane >= o) s += u;
    }
    sh[t] = s;
    __syncthreads();
    int add = (wid == 1) ? sh[31] : 0;
    if (t < SCAN_NB) g_bpre[t] = s + add - v;   // exclusive
}

// ---------------- 2c) downsweep: per-block exclusive scan + offsets --------
__global__ __launch_bounds__(SCAN_TPB) void scan3_kernel() {
    int t = threadIdx.x;
    int base = blockIdx.x * SCAN_PER_BLK + t * SCAN_CH;
    int c[SCAN_CH];
    int s = 0;
    #pragma unroll
    for (int j = 0; j < SCAN_CH; j++) {
        int idx = base + j;
        c[j] = (idx < NN) ? g_cnt[idx] : 0;
        s += c[j];
    }
    int lane = t & 31, wid = t >> 5;
    int v = s;
    #pragma unroll
    for (int o = 1; o < 32; o <<= 1) {
        int u = __shfl_up_sync(0xffffffffu, v, o);
        if (lane >= o) v += u;
    }
    __shared__ int wsum[SCAN_TPB / 32];
    if (lane == 31) wsum[wid] = v;
    __syncthreads();
    if (wid == 0) {
        int w = (lane < SCAN_TPB / 32) ? wsum[lane] : 0;
        #pragma unroll
        for (int o = 1; o < SCAN_TPB / 32; o <<= 1) {
            int u = __shfl_up_sync(0xffffffffu, w, o);
            if (lane >= o) w += u;
        }
        if (lane < SCAN_TPB / 32) wsum[lane] = w;
    }
    __syncthreads();
    int pre = v - s + (wid > 0 ? wsum[wid - 1] : 0) + g_bpre[blockIdx.x];
    #pragma unroll
    for (int j = 0; j < SCAN_CH; j++) {
        int idx = base + j;
        if (idx < NN) {
            g_off[idx] = pre;
            g_cur[idx] = pre;
        }
        pre += c[j];
    }
}

// ---------------- 3) counting-sort edges by dst (4 edges / thread) ---------
__global__ void sort_kernel(const void* __restrict__ ei) {
    int q = blockIdx.x * blockDim.x + threadIdx.x;   // quad index
    if (q >= EE / 4) return;
    int s0, s1, s2, s3, d0, d1, d2, d3;
    if (g_is64) {
        const long long* base = (const long long*)ei;
        const longlong2* ps = (const longlong2*)base;
        const longlong2* pd = (const longlong2*)(base + EE);
        longlong2 sa = ps[q * 2 + 0], sb = ps[q * 2 + 1];
        longlong2 da = pd[q * 2 + 0], db = pd[q * 2 + 1];
        s0 = (int)sa.x; s1 = (int)sa.y; s2 = (int)sb.x; s3 = (int)sb.y;
        d0 = (int)da.x; d1 = (int)da.y; d2 = (int)db.x; d3 = (int)db.y;
    } else {
        const int* base = (const int*)ei;
        int4 sa = ((const int4*)base)[q];
        int4 da = ((const int4*)(base + EE))[q];
        s0 = sa.x; s1 = sa.y; s2 = sa.z; s3 = sa.w;
        d0 = da.x; d1 = da.y; d2 = da.z; d3 = da.w;
    }
    g_srcs[atomicAdd(&g_cur[d0], 1)] = s0;
    g_srcs[atomicAdd(&g_cur[d1], 1)] = s1;
    g_srcs[atomicAdd(&g_cur[d2], 1)] = s2;
    g_srcs[atomicAdd(&g_cur[d3], 1)] = s3;
}

// ---------------- 4) segment reduce over fp16 rows -> fp32 mean -------------
// One warp per node; lane handles features {2*lane, 2*lane+1} via one __half2
// load per row (128B/row fully coalesced). Accumulate fp32.
__global__ __launch_bounds__(256) void agg_kernel() {
    int n = blockIdx.x * 8 + (threadIdx.x >> 5);
    if (n >= NN) return;
    int lane = threadIdx.x & 31;
    int off = g_off[n];
    int c   = g_cnt[n];
    float a0 = 0.0f, a1 = 0.0f;
    int e = 0;
    for (; e + 4 <= c; e += 4) {
        int s0 = g_srcs[off + e + 0];
        int s1 = g_srcs[off + e + 1];
        int s2 = g_srcs[off + e + 2];
        int s3 = g_srcs[off + e + 3];
        float2 v0 = __half22float2(g_xh[s0 * 32 + lane]);
        float2 v1 = __half22float2(g_xh[s1 * 32 + lane]);
        float2 v2 = __half22float2(g_xh[s2 * 32 + lane]);
        float2 v3 = __half22float2(g_xh[s3 * 32 + lane]);
        a0 += v0.x + v1.x;  a1 += v0.y + v1.y;
        a0 += v2.x + v3.x;  a1 += v2.y + v3.y;
    }
    for (; e < c; e++) {
        int s = g_srcs[off + e];
        float2 v = __half22float2(g_xh[s * 32 + lane]);
        a0 += v.x;
        a1 += v.y;
    }
    float inv = 1.0f / (float)(c > 1 ? c : 1);
    *(float2*)&g_mean[n * DD + 2 * lane] = make_float2(a0 * inv, a1 * inv);
}

// ---------------- 5a) gemmx: g_h = x @ Wr^T  (K=64; runs on forked stream) -
#define PITCH 68
__global__ __launch_bounds__(256) void gemmx_kernel(const float* __restrict__ x) {
    extern __shared__ float sm[];
    float* Ws = sm;                   // [64][PITCH]
    float* As = sm + 64 * PITCH;      // [64][PITCH]  k-major: As[k][n]

    int t  = threadIdx.x;
    int tx = t & 15;                  // node group (4 nodes)
    int ty = t >> 4;                  // output-feature group (4 feats)
    int n0 = blockIdx.x * 64;

    #pragma unroll
    for (int i = 0; i < 16; i++) {
        int idx = t + i * 256;        // 0..4095
        int k = idx >> 6, d = idx & 63;
        Ws[k * PITCH + d] = g_WT[4096 + idx];          // Wr^T block
    }
    #pragma unroll
    for (int i = 0; i < 16; i++) {
        int idx = t + i * 256;        // 0..4095
        int n = idx >> 6, k = idx & 63;
        int gn = n0 + n;
        As[k * PITCH + n] = (gn < NN) ? x[gn * DD + k] : 0.0f;
    }
    __syncthreads();

    float acc[4][4];
    #pragma unroll
    for (int i = 0; i < 4; i++)
        #pragma unroll
        for (int j = 0; j < 4; j++) acc[i][j] = 0.0f;

    #pragma unroll 8
    for (int k = 0; k < 64; k++) {
        float4 av = *(const float4*)&As[k * PITCH + tx * 4];
        float4 wv = *(const float4*)&Ws[k * PITCH + ty * 4];
        float a[4] = {av.x, av.y, av.z, av.w};
        float w[4] = {wv.x, wv.y, wv.z, wv.w};
        #pragma unroll
        for (int i = 0; i < 4; i++)
            #pragma unroll
            for (int j = 0; j < 4; j++)
                acc[i][j] = fmaf(a[i], w[j], acc[i][j]);
    }

    #pragma unroll
    for (int i = 0; i < 4; i++) {
        int n = n0 + tx * 4 + i;
        if (n < NN) {
            float4 o = make_float4(acc[i][0], acc[i][1], acc[i][2], acc[i][3]);
            *(float4*)&g_h[n * DD + ty * 4] = o;
        }
    }
}

// ---------------- 5b) gemm_main: h = relu(g_h + mean@Wl^T + bl) + BN stats -
__global__ __launch_bounds__(256) void gemm_main_kernel(const float* __restrict__ bl) {
    extern __shared__ float sm[];
    float* Ws = sm;                   // [64][PITCH]
    float* As = sm + 64 * PITCH;      // [64][PITCH]

    int t  = threadIdx.x;
    int tx = t & 15;
    int ty = t >> 4;
    int n0 = blockIdx.x * 64;

    #pragma unroll
    for (int i = 0; i < 16; i++) {
        int idx = t + i * 256;        // 0..4095
        int k = idx >> 6, d = idx & 63;
        Ws[k * PITCH + d] = g_WT[idx];                 // Wl^T block
    }
    #pragma unroll
    for (int i = 0; i < 16; i++) {
        int idx = t + i * 256;        // 0..4095
        int n = idx >> 6, k = idx & 63;
        int gn = n0 + n;
        As[k * PITCH + n] = (gn < NN) ? g_mean[gn * DD + k] : 0.0f;
    }
    __syncthreads();

    float acc[4][4];
    #pragma unroll
    for (int i = 0; i < 4; i++)
        #pragma unroll
        for (int j = 0; j < 4; j++) acc[i][j] = 0.0f;

    #pragma unroll 8
    for (int k = 0; k < 64; k++) {
        float4 av = *(const float4*)&As[k * PITCH + tx * 4];
        float4 wv = *(const float4*)&Ws[k * PITCH + ty * 4];
        float a[4] = {av.x, av.y, av.z, av.w};
        float w[4] = {wv.x, wv.y, wv.z, wv.w};
        #pragma unroll
        for (int i = 0; i < 4; i++)
            #pragma unroll
            for (int j = 0; j < 4; j++)
                acc[i][j] = fmaf(a[i], w[j], acc[i][j]);
    }

    float4 blv = *(const float4*)&bl[ty * 4];
    float bb[4] = {blv.x, blv.y, blv.z, blv.w};
    float s[4]  = {0.f, 0.f, 0.f, 0.f};
    float q[4]  = {0.f, 0.f, 0.f, 0.f};

    #pragma unroll
    for (int i = 0; i < 4; i++) {
        int n = n0 + tx * 4 + i;
        if (n < NN) {
            float4 hp = *(const float4*)&g_h[n * DD + ty * 4];
            float o0 = fmaxf(acc[i][0] + bb[0] + hp.x, 0.0f);
            float o1 = fmaxf(acc[i][1] + bb[1] + hp.y, 0.0f);
            float o2 = fmaxf(acc[i][2] + bb[2] + hp.z, 0.0f);
            float o3 = fmaxf(acc[i][3] + bb[3] + hp.w, 0.0f);
            s[0] += o0; q[0] += o0 * o0;
            s[1] += o1; q[1] += o1 * o1;
            s[2] += o2; q[2] += o2 * o2;
            s[3] += o3; q[3] += o3 * o3;
            float4 o = make_float4(o0, o1, o2, o3);
            *(float4*)&g_h[n * DD + ty * 4] = o;
        }
    }

    #pragma unroll
    for (int j = 0; j < 4; j++) {
        #pragma unroll
        for (int o = 8; o > 0; o >>= 1) {
            s[j] += __shfl_down_sync(0xffffffffu, s[j], o, 16);
            q[j] += __shfl_down_sync(0xffffffffu, q[j], o, 16);
        }
    }
    if (tx == 0) {
        #pragma unroll
        for (int j = 0; j < 4; j++) {
            int d = ty * 4 + j;
            atomicAdd(&g_bn[d],      s[j]);
            atomicAdd(&g_bn[64 + d], q[j]);
        }
    }
}

// ---------------- 6) fold BN into per-feature scale/shift ----------------
__global__ void bnprep_kernel(const float* __restrict__ gamma,
                              const float* __restrict__ beta) {
    int d = threadIdx.x;
    if (d < DD) {
        const float invN = 1.0f / (float)NN;
        float mu  = g_bn[d] * invN;
        float var = fmaxf(g_bn[DD + d] * invN - mu * mu, 0.0f);
        float sc  = gamma[d] * rsqrtf(var + BN_EPS);
        g_bnsc[d] = sc;
        g_bnsh[d] = beta[d] - mu * sc;
    }
}

// ---------------- 7) finalize: out = x + h*scale + shift (pure FMA) --------
__global__ void finalize_kernel(const float* __restrict__ x,
                                float* __restrict__ out) {
    int i = blockIdx.x * blockDim.x + threadIdx.x;   // float4 index
    if (i >= NN * DD / 4) return;
    int d0 = (i * 4) & 63;
    float4 h4 = *((const float4*)g_h + i);
    float4 x4 = *((const float4*)x + i);
    float4 sc = *(const float4*)&g_bnsc[d0];
    float4 sh = *(const float4*)&g_bnsh[d0];
    float4 o;
    o.x = fmaf(h4.x, sc.x, x4.x + sh.x);
    o.y = fmaf(h4.y, sc.y, x4.y + sh.y);
    o.z = fmaf(h4.z, sc.z, x4.z + sh.z);
    o.w = fmaf(h4.w, sc.w, x4.w + sh.w);
    *((float4*)out + i) = o;
}

// ---------------- launcher: fork xcvt+gemmx parallel to the edge pipeline --
// NOTE: stream/events created per call and intentionally NOT destroyed —
// destroying a stream still in capture state would invalidate the harness's
// graph capture. kernel_launch runs only a handful of times; leak is bounded.
extern "C" void kernel_launch(void* const* d_in, const int* in_sizes, int n_in,
                              void* d_out, int out_size) {
    const float* x     = (const float*)d_in[0];
    const void*  ei    = d_in[1];                 // int32 or int64, device-detected
    const float* Wl    = (const float*)d_in[2];
    const float* bl    = (const float*)d_in[3];
    const float* Wr    = (const float*)d_in[4];
    const float* gamma = (const float*)d_in[5];
    const float* beta  = (const float*)d_in[6];
    float* out = (float*)d_out;

    void *p_cnt, *p_bn;
    cudaGetSymbolAddress(&p_cnt, g_cnt);
    cudaGetSymbolAddress(&p_bn,  g_bn);
    cudaMemsetAsync(p_cnt, 0, sizeof(int) * NN);
    cudaMemsetAsync(p_bn,  0, sizeof(float) * 2 * DD);

    prep_kernel<<<2, 256>>>(ei, Wl, Wr);

    // fork: xcvt (x->fp16) then gemmx (x @ Wr^T); both independent of edges
    cudaStream_t s2;
    cudaEvent_t evFork, evCvt, evJoin;
    cudaStreamCreateWithFlags(&s2, cudaStreamNonBlocking);
    cudaEventCreateWithFlags(&evFork, cudaEventDisableTiming);
    cudaEventCreateWithFlags(&evCvt,  cudaEventDisableTiming);
    cudaEventCreateWithFlags(&evJoin, cudaEventDisableTiming);

    cudaEventRecord(evFork, 0);
    cudaStreamWaitEvent(s2, evFork, 0);

    xcvt_kernel<<<(NN * DD / 4 + 255) / 256, 256, 0, s2>>>(x);
    cudaEventRecord(evCvt, s2);

    const int smem_bytes = 2 * 64 * PITCH * (int)sizeof(float);
    gemmx_kernel<<<(NN + 63) / 64, 256, smem_bytes, s2>>>(x);
    cudaEventRecord(evJoin, s2);

    // edge pipeline on the main stream
    int qb = (EE / 4 + 255) / 256;
    count_kernel<<<qb, 256>>>(ei);
    scan1_kernel<<<SCAN_NB, SCAN_TPB>>>();
    scan2_kernel<<<1, 64>>>();
    scan3_kernel<<<SCAN_NB, SCAN_TPB>>>();
    sort_kernel<<<qb, 256>>>(ei);

    // agg needs the fp16 copy
    cudaStreamWaitEvent(0, evCvt, 0);
    agg_kernel<<<(NN + 7) / 8, 256>>>();

    // join, then the dependent half of the GEMM
    cudaStreamWaitEvent(0, evJoin, 0);
    gemm_main_kernel<<<(NN + 63) / 64, 256, smem_bytes>>>(bl);

    bnprep_kernel<<<1, 64>>>(gamma, beta);
    finalize_kernel<<<(NN * DD / 4 + 255) / 256, 256>>>(x, out);
    // no stream/event destruction: see NOTE above
}

// round 16
// speedup vs baseline: 1.0998x; 1.0998x over previous
#include <cuda_runtime.h>
#include <cuda_bf16.h>
#include <cstdint>

#define NN 100000
#define EE 1600000
#define DD 64
#define BN_EPS 1e-5f

// scan decomposition: 49 blocks x 256 threads x 8 elements = 100352 >= NN
#define SCAN_CH   8
#define SCAN_TPB  256
#define SCAN_PER_BLK (SCAN_TPB * SCAN_CH)
#define SCAN_NB   ((NN + SCAN_PER_BLK - 1) / SCAN_PER_BLK)   // 49

// ---------------- scratch (no allocations allowed) ----------------
__device__ float g_mean[NN * DD];      // 25.6 MB  mean-aggregated neighbor feats
__device__ float g_h   [NN * DD];      // 25.6 MB  partial / pre-BN activations
__device__ int   g_srcs[EE];           // 6.4 MB   src indices grouped by dst
__device__ int   g_cnt [NN];           // per-dst degree
__device__ int   g_off [NN];           // CSR offsets (exclusive scan of g_cnt)
__device__ int   g_cur [NN];           // scatter cursors (copy of g_off)
__device__ int   g_bsum[SCAN_NB];      // per-block count sums
__device__ float g_bn  [2 * DD];       // [0:64) sum, [64:128) sumsq
__device__ float g_WT  [2 * DD * DD];  // transposed concat [Wl^T ; Wr^T], k-major

// ---------------- per-block dtype self-detection ----------------
// Reads the first 64 int64 words of the edge buffer (first 512 bytes — valid
// under both interpretations). If data is really int32, a word has its high
// half drawn from [0,100000): P(word in [0,NN)) ~ 1e-5 per word -> over 64
// words detection is certain for random inputs. All threads must reach the
// barriers (call before any early-exit).
__device__ __forceinline__ int detect_is64(const void* ei, int t) {
    __shared__ int bad;
    if (t == 0) bad = 0;
    __syncthreads();
    if (t < 64) {
        long long v = ((const long long*)ei)[t];
        if (v < 0 || v >= NN) bad = 1;
    }
    __syncthreads();
    return bad ? 0 : 1;
}

// ---------------- prep (forked stream): W transpose only ----------------
__global__ void prep_kernel(const float* __restrict__ Wl,
                            const float* __restrict__ Wr) {
    int t = threadIdx.x;
    #pragma unroll
    for (int i = 0; i < 16; i++) {
        int idx = t + i * 256;          // 0..4095
        int d = idx >> 6, k = idx & 63;
        g_WT[k * 64 + d]        = Wl[idx];   // Wl[d][k]
        g_WT[(64 + k) * 64 + d] = Wr[idx];   // Wr[d][k]
    }
}

// ---------------- 1) per-dst degree count (4 edges / thread) ----------------
__global__ void count_kernel(const void* __restrict__ ei) {
    int is64 = detect_is64(ei, threadIdx.x);
    int q = blockIdx.x * blockDim.x + threadIdx.x;   // quad index
    if (q >= EE / 4) return;
    int d0, d1, d2, d3;
    if (is64) {
        const longlong2* p = (const longlong2*)((const long long*)ei + EE);
        longlong2 a = p[q * 2 + 0];
        longlong2 b = p[q * 2 + 1];
        d0 = (int)a.x; d1 = (int)a.y; d2 = (int)b.x; d3 = (int)b.y;
    } else {
        int4 a = ((const int4*)((const int*)ei + EE))[q];
        d0 = a.x; d1 = a.y; d2 = a.z; d3 = a.w;
    }
    atomicAdd(&g_cnt[d0], 1);
    atomicAdd(&g_cnt[d1], 1);
    atomicAdd(&g_cnt[d2], 1);
    atomicAdd(&g_cnt[d3], 1);
}

// ---------------- 2a) per-block sums of counts (+ zero g_bn in block 0) ----
__global__ __launch_bounds__(SCAN_TPB) void scan1_kernel() {
    int t = threadIdx.x;
    if (blockIdx.x == 0 && t < 2 * DD) g_bn[t] = 0.0f;
    int base = blockIdx.x * SCAN_PER_BLK + t * SCAN_CH;
    int s = 0;
    #pragma unroll
    for (int j = 0; j < SCAN_CH; j++) {
        int idx = base + j;
        if (idx < NN) s += g_cnt[idx];
    }
    int lane = t & 31, wid = t >> 5;
    #pragma unroll
    for (int o = 16; o > 0; o >>= 1) s += __shfl_down_sync(0xffffffffu, s, o);
    __shared__ int ws[SCAN_TPB / 32];
    if (lane == 0) ws[wid] = s;
    __syncthreads();
    if (t == 0) {
        int tot = 0;
        #pragma unroll
        for (int w = 0; w < SCAN_TPB / 32; w++) tot += ws[w];
        g_bsum[blockIdx.x] = tot;
    }
}

// ---------------- 2b) downsweep: block prefix (inline) + offsets -----------
__global__ __launch_bounds__(SCAN_TPB) void scan3_kernel() {
    int t = threadIdx.x;
    __shared__ int s_bpre;

    // warp 0 computes this block's exclusive prefix over g_bsum (redundantly
    // per block; 49 L2-broadcast loads, ~free) while others load counts
    if (t < 32) {
        int bid = blockIdx.x;
        int b0 = (t < SCAN_NB && t < bid) ? g_bsum[t] : 0;
        int t2 = t + 32;
        int b1 = (t2 < SCAN_NB && t2 < bid) ? g_bsum[t2] : 0;
        int v2 = b0 + b1;
        #pragma unroll
        for (int o = 16; o > 0; o >>= 1) v2 += __shfl_down_sync(0xffffffffu, v2, o);
        if (t == 0) s_bpre = v2;
    }

    int base = blockIdx.x * SCAN_PER_BLK + t * SCAN_CH;
    int c[SCAN_CH];
    int s = 0;
    #pragma unroll
    for (int j = 0; j < SCAN_CH; j++) {
        int idx = base + j;
        c[j] = (idx < NN) ? g_cnt[idx] : 0;
        s += c[j];
    }
    int lane = t & 31, wid = t >> 5;
    int v = s;
    #pragma unroll
    for (int o = 1; o < 32; o <<= 1) {
        int u = __shfl_up_sync(0xffffffffu, v, o);
        if (lane >= o) v += u;
    }
    __shared__ int wsum[SCAN_TPB / 32];
    if (lane == 31) wsum[wid] = v;
    __syncthreads();
    // cross-warp scan: FULL warp 0 participates (inactive lanes carry 0)
    if (wid == 0) {
        int w = (lane < SCAN_TPB / 32) ? wsum[lane] : 0;
        #pragma unroll
        for (int o = 1; o < SCAN_TPB / 32; o <<= 1) {
            int u = __shfl_up_sync(0xffffffffu, w, o);
            if (lane >= o) w += u;
        }
        if (lane < SCAN_TPB / 32) wsum[lane] = w;
    }
    __syncthreads();
    int pre = v - s + (wid > 0 ? wsum[wid - 1] : 0) + s_bpre;
    #pragma unroll
    for (int j = 0; j < SCAN_CH; j++) {
        int idx = base + j;
        if (idx < NN) {
            g_off[idx] = pre;
            g_cur[idx] = pre;
        }
        pre += c[j];
    }
}

// ---------------- 3) counting-sort edges by dst (4 edges / thread) ---------
__global__ void sort_kernel(const void* __restrict__ ei) {
    int is64 = detect_is64(ei, threadIdx.x);
    int q = blockIdx.x * blockDim.x + threadIdx.x;   // quad index
    if (q >= EE / 4) return;
    int s0, s1, s2, s3, d0, d1, d2, d3;
    if (is64) {
        const long long* base = (const long long*)ei;
        const longlong2* ps = (const longlong2*)base;
        const longlong2* pd = (const longlong2*)(base + EE);
        longlong2 sa = ps[q * 2 + 0], sb = ps[q * 2 + 1];
        longlong2 da = pd[q * 2 + 0], db = pd[q * 2 + 1];
        s0 = (int)sa.x; s1 = (int)sa.y; s2 = (int)sb.x; s3 = (int)sb.y;
        d0 = (int)da.x; d1 = (int)da.y; d2 = (int)db.x; d3 = (int)db.y;
    } else {
        const int* base = (const int*)ei;
        int4 sa = ((const int4*)base)[q];
        int4 da = ((const int4*)(base + EE))[q];
        s0 = sa.x; s1 = sa.y; s2 = sa.z; s3 = sa.w;
        d0 = da.x; d1 = da.y; d2 = da.z; d3 = da.w;
    }
    g_srcs[atomicAdd(&g_cur[d0], 1)] = s0;
    g_srcs[atomicAdd(&g_cur[d1], 1)] = s1;
    g_srcs[atomicAdd(&g_cur[d2], 1)] = s2;
    g_srcs[atomicAdd(&g_cur[d3], 1)] = s3;
}

// ---------------- 4) segment reduce: mean neighbor features (fp32) ---------
// One warp per node; lane handles features {lane, lane+32}. No atomics.
__global__ __launch_bounds__(256) void agg_kernel(const float* __restrict__ x) {
    int n = blockIdx.x * 8 + (threadIdx.x >> 5);
    if (n >= NN) return;
    int lane = threadIdx.x & 31;
    int off = g_off[n];
    int c   = g_cnt[n];
    float a0 = 0.0f, a1 = 0.0f;
    int e = 0;
    for (; e + 4 <= c; e += 4) {
        int s0 = g_srcs[off + e + 0];
        int s1 = g_srcs[off + e + 1];
        int s2 = g_srcs[off + e + 2];
        int s3 = g_srcs[off + e + 3];
        a0 += x[s0 * DD + lane]      + x[s1 * DD + lane];
        a1 += x[s0 * DD + 32 + lane] + x[s1 * DD + 32 + lane];
        a0 += x[s2 * DD + lane]      + x[s3 * DD + lane];
        a1 += x[s2 * DD + 32 + lane] + x[s3 * DD + 32 + lane];
    }
    for (; e < c; e++) {
        int s = g_srcs[off + e];
        a0 += x[s * DD + lane];
        a1 += x[s * DD + 32 + lane];
    }
    float inv = 1.0f / (float)(c > 1 ? c : 1);
    g_mean[n * DD + lane]      = a0 * inv;
    g_mean[n * DD + 32 + lane] = a1 * inv;
}

// ---------------- 5a) gemmx: g_h = x @ Wr^T  (K=64; runs on forked stream) -
#define PITCH 68
__global__ __launch_bounds__(256) void gemmx_kernel(const float* __restrict__ x) {
    extern __shared__ float sm[];
    float* Ws = sm;                   // [64][PITCH]
    float* As = sm + 64 * PITCH;      // [64][PITCH]  k-major: As[k][n]

    int t  = threadIdx.x;
    int tx = t & 15;                  // node group (4 nodes)
    int ty = t >> 4;                  // output-feature group (4 feats)
    int n0 = blockIdx.x * 64;

    #pragma unroll
    for (int i = 0; i < 16; i++) {
        int idx = t + i * 256;        // 0..4095
        int k = idx >> 6, d = idx & 63;
        Ws[k * PITCH + d] = g_WT[4096 + idx];          // Wr^T block
    }
    #pragma unroll
    for (int i = 0; i < 16; i++) {
        int idx = t + i * 256;        // 0..4095
        int n = idx >> 6, k = idx & 63;
        int gn = n0 + n;
        As[k * PITCH + n] = (gn < NN) ? x[gn * DD + k] : 0.0f;
    }
    __syncthreads();

    float acc[4][4];
    #pragma unroll
    for (int i = 0; i < 4; i++)
        #pragma unroll
        for (int j = 0; j < 4; j++) acc[i][j] = 0.0f;

    #pragma unroll 8
    for (int k = 0; k < 64; k++) {
        float4 av = *(const float4*)&As[k * PITCH + tx * 4];
        float4 wv = *(const float4*)&Ws[k * PITCH + ty * 4];
        float a[4] = {av.x, av.y, av.z, av.w};
        float w[4] = {wv.x, wv.y, wv.z, wv.w};
        #pragma unroll
        for (int i = 0; i < 4; i++)
            #pragma unroll
            for (int j = 0; j < 4; j++)
                acc[i][j] = fmaf(a[i], w[j], acc[i][j]);
    }

    #pragma unroll
    for (int i = 0; i < 4; i++) {
        int n = n0 + tx * 4 + i;
        if (n < NN) {
            float4 o = make_float4(acc[i][0], acc[i][1], acc[i][2], acc[i][3]);
            *(float4*)&g_h[n * DD + ty * 4] = o;
        }
    }
}

// ---------------- 5b) gemm_main: h = relu(g_h + mean@Wl^T + bl) + BN stats -
__global__ __launch_bounds__(256) void gemm_main_kernel(const float* __restrict__ bl) {
    extern __shared__ float sm[];
    float* Ws = sm;                   // [64][PITCH]
    float* As = sm + 64 * PITCH;      // [64][PITCH]

    int t  = threadIdx.x;
    int tx = t & 15;
    int ty = t >> 4;
    int n0 = blockIdx.x * 64;

    #pragma unroll
    for (int i = 0; i < 16; i++) {
        int idx = t + i * 256;        // 0..4095
        int k = idx >> 6, d = idx & 63;
        Ws[k * PITCH + d] = g_WT[idx];                 // Wl^T block
    }
    #pragma unroll
    for (int i = 0; i < 16; i++) {
        int idx = t + i * 256;        // 0..4095
        int n = idx >> 6, k = idx & 63;
        int gn = n0 + n;
        As[k * PITCH + n] = (gn < NN) ? g_mean[gn * DD + k] : 0.0f;
    }
    __syncthreads();

    float acc[4][4];
    #pragma unroll
    for (int i = 0; i < 4; i++)
        #pragma unroll
        for (int j = 0; j < 4; j++) acc[i][j] = 0.0f;

    #pragma unroll 8
    for (int k = 0; k < 64; k++) {
        float4 av = *(const float4*)&As[k * PITCH + tx * 4];
        float4 wv = *(const float4*)&Ws[k * PITCH + ty * 4];
        float a[4] = {av.x, av.y, av.z, av.w};
        float w[4] = {wv.x, wv.y, wv.z, wv.w};
        #pragma unroll
        for (int i = 0; i < 4; i++)
            #pragma unroll
            for (int j = 0; j < 4; j++)
                acc[i][j] = fmaf(a[i], w[j], acc[i][j]);
    }

    float4 blv = *(const float4*)&bl[ty * 4];
    float bb[4] = {blv.x, blv.y, blv.z, blv.w};
    float s[4]  = {0.f, 0.f, 0.f, 0.f};
    float q[4]  = {0.f, 0.f, 0.f, 0.f};

    #pragma unroll
    for (int i = 0; i < 4; i++) {
        int n = n0 + tx * 4 + i;
        if (n < NN) {
            float4 hp = *(const float4*)&g_h[n * DD + ty * 4];
            float o0 = fmaxf(acc[i][0] + bb[0] + hp.x, 0.0f);
            float o1 = fmaxf(acc[i][1] + bb[1] + hp.y, 0.0f);
            float o2 = fmaxf(acc[i][2] + bb[2] + hp.z, 0.0f);
            float o3 = fmaxf(acc[i][3] + bb[3] + hp.w, 0.0f);
            s[0] += o0; q[0] += o0 * o0;
            s[1] += o1; q[1] += o1 * o1;
            s[2] += o2; q[2] += o2 * o2;
            s[3] += o3; q[3] += o3 * o3;
            float4 o = make_float4(o0, o1, o2, o3);
            *(float4*)&g_h[n * DD + ty * 4] = o;
        }
    }

    #pragma unroll
    for (int j = 0; j < 4; j++) {
        #pragma unroll
        for (int o = 8; o > 0; o >>= 1) {
            s[j] += __shfl_down_sync(0xffffffffu, s[j], o, 16);
            q[j] += __shfl_down_sync(0xffffffffu, q[j], o, 16);
        }
    }
    if (tx == 0) {
        #pragma unroll
        for (int j = 0; j < 4; j++) {
            int d = ty * 4 + j;
            atomicAdd(&g_bn[d],      s[j]);
            atomicAdd(&g_bn[64 + d], q[j]);
        }
    }
}

// ---------------- 6) finalize (BN fold inlined): out = x + h*sc + sh -------
__global__ void finalize_kernel(const float* __restrict__ x,
                                const float* __restrict__ gamma,
                                const float* __restrict__ beta,
                                float* __restrict__ out) {
    __shared__ float s_sc[DD], s_sh[DD];
    int t = threadIdx.x;
    if (t < DD) {
        const float invN = 1.0f / (float)NN;
        float mu  = g_bn[t] * invN;
        float var = fmaxf(g_bn[DD + t] * invN - mu * mu, 0.0f);
        float sc  = gamma[t] * rsqrtf(var + BN_EPS);
        s_sc[t] = sc;
        s_sh[t] = beta[t] - mu * sc;
    }
    __syncthreads();
    int i = blockIdx.x * blockDim.x + t;             // float4 index
    if (i >= NN * DD / 4) return;
    int d0 = (i * 4) & 63;
    float4 h4 = *((const float4*)g_h + i);
    float4 x4 = *((const float4*)x + i);
    float4 sc = *(float4*)&s_sc[d0];
    float4 sh = *(float4*)&s_sh[d0];
    float4 o;
    o.x = fmaf(h4.x, sc.x, x4.x + sh.x);
    o.y = fmaf(h4.y, sc.y, x4.y + sh.y);
    o.z = fmaf(h4.z, sc.z, x4.z + sh.z);
    o.w = fmaf(h4.w, sc.w, x4.w + sh.w);
    *((float4*)out + i) = o;
}

// ---------------- launcher: 7 serial nodes + forked (prep, gemmx) ----------
// NOTE: stream/events created per call and intentionally NOT destroyed —
// destroying a stream still in capture state would invalidate the harness's
// graph capture. kernel_launch runs only a handful of times; leak is bounded.
extern "C" void kernel_launch(void* const* d_in, const int* in_sizes, int n_in,
                              void* d_out, int out_size) {
    const float* x     = (const float*)d_in[0];
    const void*  ei    = d_in[1];                 // int32 or int64, self-detected
    const float* Wl    = (const float*)d_in[2];
    const float* bl    = (const float*)d_in[3];
    const float* Wr    = (const float*)d_in[4];
    const float* gamma = (const float*)d_in[5];
    const float* beta  = (const float*)d_in[6];
    float* out = (float*)d_out;

    void* p_cnt;
    cudaGetSymbolAddress(&p_cnt, g_cnt);
    cudaMemsetAsync(p_cnt, 0, sizeof(int) * NN);

    // fork: prep (W transpose) then gemmx (x @ Wr^T); independent of edges
    cudaStream_t s2;
    cudaEvent_t evFork, evJoin;
    cudaStreamCreateWithFlags(&s2, cudaStreamNonBlocking);
    cudaEventCreateWithFlags(&evFork, cudaEventDisableTiming);
    cudaEventCreateWithFlags(&evJoin, cudaEventDisableTiming);

    cudaEventRecord(evFork, 0);
    cudaStreamWaitEvent(s2, evFork, 0);

    prep_kernel<<<1, 256, 0, s2>>>(Wl, Wr);
    const int smem_bytes = 2 * 64 * PITCH * (int)sizeof(float);
    gemmx_kernel<<<(NN + 63) / 64, 256, smem_bytes, s2>>>(x);
    cudaEventRecord(evJoin, s2);

    // edge pipeline on the main stream
    int qb = (EE / 4 + 255) / 256;
    count_kernel<<<qb, 256>>>(ei);
    scan1_kernel<<<SCAN_NB, SCAN_TPB>>>();
    scan3_kernel<<<SCAN_NB, SCAN_TPB>>>();
    sort_kernel<<<qb, 256>>>(ei);
    agg_kernel<<<(NN + 7) / 8, 256>>>(x);

    // join, then the dependent half of the GEMM
    cudaStreamWaitEvent(0, evJoin, 0);
    gemm_main_kernel<<<(NN + 63) / 64, 256, smem_bytes>>>(bl);

    finalize_kernel<<<(NN * DD / 4 + 255) / 256, 256>>>(x, gamma, beta, out);
    // no stream/event destruction: see NOTE above
}